// round 15
// baseline (speedup 1.0000x reference)
#include <cuda_runtime.h>
#include <cuda_fp16.h>

#define T_LEN 2048
#define HD    2048
#define G4    8192
#define NV    128
#define WSZ   (8192ull*2048ull)
#define REC_CTAS 148
#define UNITS_MAX 14
#define SMEM_REC (UNITS_MAX*4*HD*2)     // 229376 bytes: all weights smem-resident

// ---------------- device scratch ----------------
__device__ __half g_xh [(size_t)T_LEN*HD];
__device__ __half g_wih[2*WSZ];
__device__ __half g_whh[2*WSZ];
__device__ __half g_fcw[(size_t)NV*HD];
__device__ float  g_xg [(size_t)T_LEN*G4];   // layout [t][j][gate]
__device__ __half g_h1 [(size_t)T_LEN*HD];
__device__ __half g_h2 [(size_t)T_LEN*HD];
__device__ float  g_hN [2*HD];
__device__ float  g_cN [2*HD];
__device__ __align__(16) __half g_h0h[2][HD];
__device__ unsigned g_cnt;                   // cumulative across layers; reset per invocation

__device__ __forceinline__ void red_add_u32(unsigned* p, unsigned v) {
    asm volatile("red.global.add.u32 [%0], %1;" :: "l"(p), "r"(v) : "memory");
}

// ---------------- fp32 -> fp16 conversion (+ per-invocation barrier reset) ----------------
__global__ void cvt_inputs(const float* __restrict__ x,
                           const float* __restrict__ wih,
                           const float* __restrict__ whh,
                           const float* __restrict__ fcw) {
    if (blockIdx.x == 0 && threadIdx.x == 0) g_cnt = 0;
    const size_t n = 2*WSZ;
    for (size_t i = (size_t)blockIdx.x*blockDim.x + threadIdx.x; i < n;
         i += (size_t)gridDim.x*blockDim.x) {
        g_wih[i] = __float2half(wih[i]);
        g_whh[i] = __float2half(whh[i]);
        if (i < (size_t)T_LEN*HD) g_xh[i]  = __float2half(x[i]);
        if (i < (size_t)NV*HD)    g_fcw[i] = __float2half(fcw[i]);
    }
}

// ---------------- HMMA GEMM: Xg = A @ W_ih^T + (b_ih + b_hh) ----------------
__device__ __forceinline__ void mma_16816(float d[4], const unsigned a[4], const unsigned b[2]) {
    asm volatile(
        "mma.sync.aligned.m16n8k16.row.col.f32.f16.f16.f32 "
        "{%0,%1,%2,%3}, {%4,%5,%6,%7}, {%8,%9}, {%0,%1,%2,%3};\n"
        : "+f"(d[0]), "+f"(d[1]), "+f"(d[2]), "+f"(d[3])
        : "r"(a[0]), "r"(a[1]), "r"(a[2]), "r"(a[3]), "r"(b[0]), "r"(b[1]));
}

__global__ void __launch_bounds__(256) gemm_ih(int layer,
                                               const float* __restrict__ bih_all,
                                               const float* __restrict__ bhh_all) {
    const __half* A = (layer == 0) ? g_xh : g_h1;
    const __half* B = g_wih + (size_t)layer*WSZ;
    const float*  bi = bih_all + layer*G4;
    const float*  bh = bhh_all + layer*G4;

    __shared__ __half As[128][40];
    __shared__ __half Bs[128][40];

    const int tid  = threadIdx.x;
    const int bn   = blockIdx.x * 128;
    const int bm   = blockIdx.y * 128;
    const int warp = tid >> 5, lane = tid & 31;
    const int wm = (warp >> 2) * 64, wn = (warp & 3) * 32;
    const int g = lane >> 2, tq = lane & 3;

    float acc[4][4][4];
    #pragma unroll
    for (int a = 0; a < 4; ++a)
        #pragma unroll
        for (int b = 0; b < 4; ++b)
            #pragma unroll
            for (int c = 0; c < 4; ++c) acc[a][b][c] = 0.f;

    for (int k0 = 0; k0 < HD; k0 += 32) {
        #pragma unroll
        for (int c = 0; c < 2; ++c) {
            int idx = tid + c*256;
            int r = idx >> 2, cc = (idx & 3) * 8;
            *(uint4*)&As[r][cc] = *(const uint4*)(A + (size_t)(bm + r)*HD + k0 + cc);
            *(uint4*)&Bs[r][cc] = *(const uint4*)(B + (size_t)(bn + r)*HD + k0 + cc);
        }
        __syncthreads();
        #pragma unroll
        for (int kk = 0; kk < 32; kk += 16) {
            unsigned af[4][4], bf[4][2];
            #pragma unroll
            for (int mt = 0; mt < 4; ++mt) {
                int r = wm + mt*16 + g;
                af[mt][0] = *(const unsigned*)&As[r  ][kk + 2*tq];
                af[mt][1] = *(const unsigned*)&As[r+8][kk + 2*tq];
                af[mt][2] = *(const unsigned*)&As[r  ][kk + 2*tq + 8];
                af[mt][3] = *(const unsigned*)&As[r+8][kk + 2*tq + 8];
            }
            #pragma unroll
            for (int nt = 0; nt < 4; ++nt) {
                int r = wn + nt*8 + g;
                bf[nt][0] = *(const unsigned*)&Bs[r][kk + 2*tq];
                bf[nt][1] = *(const unsigned*)&Bs[r][kk + 2*tq + 8];
            }
            #pragma unroll
            for (int mt = 0; mt < 4; ++mt)
                #pragma unroll
                for (int nt = 0; nt < 4; ++nt)
                    mma_16816(acc[mt][nt], af[mt], bf[nt]);
        }
        __syncthreads();
    }

    // Gate-interleaved epilogue: g_xg[row*G4 + j*4 + gate]
    #pragma unroll
    for (int mt = 0; mt < 4; ++mt) {
        #pragma unroll
        for (int nt = 0; nt < 4; ++nt) {
            int row = bm + wm + mt*16 + g;
            int col = bn + wn + nt*8 + 2*tq;
            int gate = col >> 11;
            int j    = col & 2047;
            float b0 = bi[col]   + bh[col];
            float b1 = bi[col+1] + bh[col+1];
            size_t i0  = (size_t)row*G4 + ((size_t)j << 2) + gate;
            size_t i08 = i0 + (size_t)8*G4;
            g_xg[i0]      = acc[mt][nt][0] + b0;
            g_xg[i0 + 4]  = acc[mt][nt][1] + b1;
            g_xg[i08]     = acc[mt][nt][2] + b0;
            g_xg[i08 + 4] = acc[mt][nt][3] + b1;
        }
    }
}

// ---------------- h0 conversion (both layers, once) ----------------
__global__ void init_h0(const float* __restrict__ h0) {
    int i = blockIdx.x*blockDim.x + threadIdx.x;
    if (i < 2*HD) g_h0h[i >> 11][i & 2047] = __float2half(h0[i]);
}

__device__ __forceinline__ float sigf(float x) { return 1.f / (1.f + __expf(-x)); }

// Fast, safe tanh: sign(x) * (1-e)/(1+e), e = exp(-2|x|) in (0,1]
__device__ __forceinline__ float tanhfast(float x) {
    float a = fabsf(x);
    float e = __expf(-2.f * a);
    float r = __fdividef(1.f - e, 1.f + e);
    return copysignf(r, x);
}

__device__ __forceinline__ float hsum4(const __half2 s[4]) {
    float2 f0 = __half22float2(s[0]);
    float2 f1 = __half22float2(s[1]);
    float2 f2 = __half22float2(s[2]);
    float2 f3 = __half22float2(s[3]);
    return ((f0.x + f0.y) + (f1.x + f1.y)) + ((f2.x + f2.y) + (f3.x + f3.y));
}

// One dot iteration: 4 gate rows x 8 halfs against hreg[it].
#define DOT_ITER(V0, V1, V2, V3, IT)                                           \
    do {                                                                       \
        const __half2* hp = (const __half2*)&hreg[IT];                         \
        const __half2* p0 = (const __half2*)&(V0);                             \
        const __half2* p1 = (const __half2*)&(V1);                             \
        const __half2* p2 = (const __half2*)&(V2);                             \
        const __half2* p3 = (const __half2*)&(V3);                             \
        _Pragma("unroll")                                                      \
        for (int k = 0; k < 4; ++k) {                                          \
            s0[k] = __hfma2(p0[k], hp[k], s0[k]);                              \
            s1[k] = __hfma2(p1[k], hp[k], s1[k]);                              \
            s2[k] = __hfma2(p2[k], hp[k], s2[k]);                              \
            s3[k] = __hfma2(p3[k], hp[k], s3[k]);                              \
        }                                                                      \
    } while (0)

// ---------------- persistent weight-stationary LSTM recurrence ----------------
// 148 CTAs, 448 threads; CTA b owns nb = 14 (b<124) or 13 units.
// Weights: iterations 0-1 (512 of 2048 elems) live in REGISTERS per warp;
// iterations 2-7 read from SMEM. Barrier: R14-proven red+volatile-poll.
__global__ void __launch_bounds__(448, 1) lstm_recur(int layer, const float* __restrict__ c0all) {
    extern __shared__ __half ws[];          // up to 14 * 4 * HD halfs

    const int tid  = threadIdx.x;
    const int lane = tid & 31;
    const int wrp  = tid >> 5;
    const int b    = blockIdx.x;
    const int nb   = (b < 124) ? 14 : 13;
    const int start = b*13 + min(b, 124);
    const int j    = start + wrp;
    const bool valid = (wrp < nb);

    const __half* Whh  = g_whh + (size_t)layer*WSZ;
    __half*       Hout = layer ? g_h2 : g_h1;

    // Stage ALL nb units' weights into smem once per layer launch.
    {
        const int totq = nb << 10;          // nb*4*2048/8 uint4
        for (int idx = tid; idx < totq; idx += 448) {
            int u   = idx >> 10;
            int rem = idx & 1023;
            int g   = rem >> 8;
            int k   = (rem & 255) << 3;
            *(uint4*)(ws + ((size_t)(u*4 + g))*HD + k) =
                *(const uint4*)(Whh + (size_t)g*HD*HD + (size_t)(start + u)*HD + k);
        }
    }

    float c = valid ? c0all[layer*HD + j] : 0.f;

    __syncthreads();

    // Preload iterations 0-1 of this warp's 4 gate rows into registers (8 uint4).
    const __half* w0 = ws + (size_t)(wrp < nb ? wrp : 0) * 4 * HD;
    const __half* w1 = w0 + HD;
    const __half* w2 = w1 + HD;
    const __half* w3 = w2 + HD;
    uint4 r00, r01, r02, r03, r10, r11, r12, r13;
    {
        const int c0i = lane*8, c1i = 256 + lane*8;
        r00 = *(const uint4*)(w0 + c0i); r01 = *(const uint4*)(w1 + c0i);
        r02 = *(const uint4*)(w2 + c0i); r03 = *(const uint4*)(w3 + c0i);
        r10 = *(const uint4*)(w0 + c1i); r11 = *(const uint4*)(w1 + c1i);
        r12 = *(const uint4*)(w2 + c1i); r13 = *(const uint4*)(w3 + c1i);
    }

    const __half2 z = __float2half2_rn(0.f);
    const unsigned base = (unsigned)layer * (unsigned)(T_LEN - 1) * (unsigned)REC_CTAS;

    for (int t = 0; t < T_LEN; ++t) {
        // lanes 0-3 prefetch this unit's 4 gate inputs (one scalar each)
        float xs = 0.f;
        if (valid && lane < 4)
            xs = __ldcg(g_xg + (size_t)t*G4 + ((size_t)j << 2) + lane);

        // h_{t-1} -> registers: 8 MLP-overlapped 16B loads per thread
        const uint4* hp4 = (const uint4*)((t == 0) ? g_h0h[layer] : (Hout + (size_t)(t-1)*HD));
        uint4 hreg[8];
        #pragma unroll
        for (int it = 0; it < 8; ++it)
            hreg[it] = __ldcg(hp4 + it*32 + lane);

        if (valid) {
            __half2 s0[4], s1[4], s2[4], s3[4];
            #pragma unroll
            for (int k = 0; k < 4; ++k) { s0[k] = z; s1[k] = z; s2[k] = z; s3[k] = z; }

            // iterations 0-1 from registers (no LDS)
            DOT_ITER(r00, r01, r02, r03, 0);
            DOT_ITER(r10, r11, r12, r13, 1);
            // iterations 2-7 from SMEM
            #pragma unroll
            for (int it = 2; it < 8; ++it) {
                const int col = it*256 + lane*8;
                uint4 v0 = *(const uint4*)(w0 + col);
                uint4 v1 = *(const uint4*)(w1 + col);
                uint4 v2 = *(const uint4*)(w2 + col);
                uint4 v3 = *(const uint4*)(w3 + col);
                DOT_ITER(v0, v1, v2, v3, it);
            }

            float a0 = hsum4(s0), a1 = hsum4(s1), a2 = hsum4(s2), a3 = hsum4(s3);
            #pragma unroll
            for (int off = 16; off; off >>= 1) {
                a0 += __shfl_xor_sync(0xffffffffu, a0, off);
                a1 += __shfl_xor_sync(0xffffffffu, a1, off);
                a2 += __shfl_xor_sync(0xffffffffu, a2, off);
                a3 += __shfl_xor_sync(0xffffffffu, a3, off);
            }
            // Parallel activations: lane g computes gate g (all lanes hold a0..a3)
            float av  = (lane == 0) ? a0 : (lane == 1) ? a1 : (lane == 2) ? a2 : a3;
            float act = (lane == 2) ? tanhfast(av + xs) : sigf(av + xs);
            float ig = __shfl_sync(0xffffffffu, act, 0);
            float fg = __shfl_sync(0xffffffffu, act, 1);
            float gg = __shfl_sync(0xffffffffu, act, 2);
            float og = __shfl_sync(0xffffffffu, act, 3);
            if (lane == 0) {
                c = fg * c + ig * gg;
                float h = og * tanhfast(c);
                Hout[(size_t)t * HD + j] = __float2half(h);
                if (t == T_LEN - 1) { g_hN[layer*HD + j] = h; g_cN[layer*HD + j] = c; }
            }
        }

        if (t + 1 < T_LEN) {
            __syncthreads();                     // all warps' h stores issued
            if (tid == 0) {
                __threadfence();                 // release: CTA's stores visible before arrive
                red_add_u32(&g_cnt, 1u);         // arrive: fire-and-forget
                const unsigned target = base + (unsigned)REC_CTAS * (unsigned)(t + 1);
                volatile unsigned* vc = &g_cnt;  // STRONG direct poll (proven)
                while (*vc < target) {}
                __threadfence();                 // acquire before next step's reads
            }
            __syncthreads();
        }
    }
}

// ---------------- FC + log_softmax: one CTA per timestep ----------------
__global__ void __launch_bounds__(128) fc_logsoftmax(const float* __restrict__ fcb,
                                                     float* __restrict__ out) {
    const int t = blockIdx.x, v = threadIdx.x;
    __shared__ __align__(16) __half hsl[HD];
    __shared__ float lg[NV];
    __shared__ float red[NV];

    const uint4* src = (const uint4*)(g_h2 + (size_t)t * HD);
    ((uint4*)hsl)[v]       = src[v];
    ((uint4*)hsl)[v + 128] = src[v + 128];
    __syncthreads();

    float acc = fcb[v];
    const __half* wr = g_fcw + (size_t)v * HD;
    #pragma unroll 4
    for (int k = 0; k < HD; k += 8) {
        uint4 wv = *(const uint4*)(wr + k);
        uint4 hv = *(const uint4*)(hsl + k);
        float2 a, bb;
        a = __half22float2(*(const __half2*)&wv.x); bb = __half22float2(*(const __half2*)&hv.x); acc += a.x*bb.x + a.y*bb.y;
        a = __half22float2(*(const __half2*)&wv.y); bb = __half22float2(*(const __half2*)&hv.y); acc += a.x*bb.x + a.y*bb.y;
        a = __half22float2(*(const __half2*)&wv.z); bb = __half22float2(*(const __half2*)&hv.z); acc += a.x*bb.x + a.y*bb.y;
        a = __half22float2(*(const __half2*)&wv.w); bb = __half22float2(*(const __half2*)&hv.w); acc += a.x*bb.x + a.y*bb.y;
    }
    lg[v] = acc; red[v] = acc;
    __syncthreads();
    for (int s = 64; s > 0; s >>= 1) { if (v < s) red[v] = fmaxf(red[v], red[v + s]); __syncthreads(); }
    float mx = red[0];
    __syncthreads();
    red[v] = __expf(lg[v] - mx);
    __syncthreads();
    for (int s = 64; s > 0; s >>= 1) { if (v < s) red[v] += red[v + s]; __syncthreads(); }
    float lse = mx + logf(red[0]);
    out[(size_t)t * NV + v] = lg[v] - lse;
}

// ---------------- optional h_n / c_n tail ----------------
__global__ void write_states(float* __restrict__ out) {
    int i = blockIdx.x*blockDim.x + threadIdx.x;
    if (i < 2*HD) {
        out[(size_t)T_LEN*NV + i]        = g_hN[i];
        out[(size_t)T_LEN*NV + 2*HD + i] = g_cN[i];
    }
}

// ---------------- launcher ----------------
extern "C" void kernel_launch(void* const* d_in, const int* in_sizes, int n_in,
                              void* d_out, int out_size) {
    const float* x   = (const float*)d_in[0];
    const float* h0  = (const float*)d_in[1];
    const float* c0  = (const float*)d_in[2];
    const float* Wih = (const float*)d_in[3];
    const float* Whh = (const float*)d_in[4];
    const float* bih = (const float*)d_in[5];
    const float* bhh = (const float*)d_in[6];
    const float* fcw = (const float*)d_in[7];
    const float* fcb = (const float*)d_in[8];
    float* out = (float*)d_out;
    (void)in_sizes; (void)n_in;

    cudaFuncSetAttribute(lstm_recur, cudaFuncAttributeMaxDynamicSharedMemorySize, SMEM_REC);

    cvt_inputs<<<2048, 256>>>(x, Wih, Whh, fcw);
    init_h0<<<16, 256>>>(h0);

    dim3 ggrid(G4/128, T_LEN/128);
    for (int l = 0; l < 2; ++l) {
        gemm_ih<<<ggrid, 256>>>(l, bih, bhh);
        lstm_recur<<<REC_CTAS, 448, SMEM_REC>>>(l, c0);
    }

    fc_logsoftmax<<<T_LEN, 128>>>(fcb, out);

    if (out_size >= T_LEN*NV + 4*HD)
        write_states<<<(2*HD + 255)/256, 256>>>(out);
}

// round 16
// speedup vs baseline: 1.2343x; 1.2343x over previous
#include <cuda_runtime.h>
#include <cuda_fp16.h>

#define T_LEN 2048
#define HD    2048
#define G4    8192
#define NV    128
#define WSZ   (8192ull*2048ull)
#define REC_CTAS 148
#define UNITS_MAX 14
#define SMEM_REC (UNITS_MAX*4*HD*2)     // 229376 bytes: all weights smem-resident

// ---------------- device scratch ----------------
__device__ __half g_xh [(size_t)T_LEN*HD];
__device__ __half g_wih[2*WSZ];
__device__ __half g_whh[2*WSZ];
__device__ __half g_fcw[(size_t)NV*HD];
__device__ float  g_xg [(size_t)T_LEN*G4];   // layout [t][j][gate]
__device__ __half g_h1 [(size_t)T_LEN*HD];
__device__ __half g_h2 [(size_t)T_LEN*HD];
__device__ float  g_hN [2*HD];
__device__ float  g_cN [2*HD];
__device__ __align__(16) __half g_h0h[2][HD];
__device__ unsigned g_cnt;                   // cumulative across layers; reset per invocation

__device__ __forceinline__ void red_add_u32(unsigned* p, unsigned v) {
    asm volatile("red.global.add.u32 [%0], %1;" :: "l"(p), "r"(v) : "memory");
}

// ---------------- fp32 -> fp16 conversion (+ per-invocation barrier reset) ----------------
__global__ void cvt_inputs(const float* __restrict__ x,
                           const float* __restrict__ wih,
                           const float* __restrict__ whh,
                           const float* __restrict__ fcw) {
    if (blockIdx.x == 0 && threadIdx.x == 0) g_cnt = 0;
    const size_t n = 2*WSZ;
    for (size_t i = (size_t)blockIdx.x*blockDim.x + threadIdx.x; i < n;
         i += (size_t)gridDim.x*blockDim.x) {
        g_wih[i] = __float2half(wih[i]);
        g_whh[i] = __float2half(whh[i]);
        if (i < (size_t)T_LEN*HD) g_xh[i]  = __float2half(x[i]);
        if (i < (size_t)NV*HD)    g_fcw[i] = __float2half(fcw[i]);
    }
}

// ---------------- HMMA GEMM: Xg = A @ W_ih^T + (b_ih + b_hh) ----------------
__device__ __forceinline__ void mma_16816(float d[4], const unsigned a[4], const unsigned b[2]) {
    asm volatile(
        "mma.sync.aligned.m16n8k16.row.col.f32.f16.f16.f32 "
        "{%0,%1,%2,%3}, {%4,%5,%6,%7}, {%8,%9}, {%0,%1,%2,%3};\n"
        : "+f"(d[0]), "+f"(d[1]), "+f"(d[2]), "+f"(d[3])
        : "r"(a[0]), "r"(a[1]), "r"(a[2]), "r"(a[3]), "r"(b[0]), "r"(b[1]));
}

__global__ void __launch_bounds__(256) gemm_ih(int layer,
                                               const float* __restrict__ bih_all,
                                               const float* __restrict__ bhh_all) {
    const __half* A = (layer == 0) ? g_xh : g_h1;
    const __half* B = g_wih + (size_t)layer*WSZ;
    const float*  bi = bih_all + layer*G4;
    const float*  bh = bhh_all + layer*G4;

    __shared__ __half As[128][40];
    __shared__ __half Bs[128][40];

    const int tid  = threadIdx.x;
    const int bn   = blockIdx.x * 128;
    const int bm   = blockIdx.y * 128;
    const int warp = tid >> 5, lane = tid & 31;
    const int wm = (warp >> 2) * 64, wn = (warp & 3) * 32;
    const int g = lane >> 2, tq = lane & 3;

    float acc[4][4][4];
    #pragma unroll
    for (int a = 0; a < 4; ++a)
        #pragma unroll
        for (int b = 0; b < 4; ++b)
            #pragma unroll
            for (int c = 0; c < 4; ++c) acc[a][b][c] = 0.f;

    for (int k0 = 0; k0 < HD; k0 += 32) {
        #pragma unroll
        for (int c = 0; c < 2; ++c) {
            int idx = tid + c*256;
            int r = idx >> 2, cc = (idx & 3) * 8;
            *(uint4*)&As[r][cc] = *(const uint4*)(A + (size_t)(bm + r)*HD + k0 + cc);
            *(uint4*)&Bs[r][cc] = *(const uint4*)(B + (size_t)(bn + r)*HD + k0 + cc);
        }
        __syncthreads();
        #pragma unroll
        for (int kk = 0; kk < 32; kk += 16) {
            unsigned af[4][4], bf[4][2];
            #pragma unroll
            for (int mt = 0; mt < 4; ++mt) {
                int r = wm + mt*16 + g;
                af[mt][0] = *(const unsigned*)&As[r  ][kk + 2*tq];
                af[mt][1] = *(const unsigned*)&As[r+8][kk + 2*tq];
                af[mt][2] = *(const unsigned*)&As[r  ][kk + 2*tq + 8];
                af[mt][3] = *(const unsigned*)&As[r+8][kk + 2*tq + 8];
            }
            #pragma unroll
            for (int nt = 0; nt < 4; ++nt) {
                int r = wn + nt*8 + g;
                bf[nt][0] = *(const unsigned*)&Bs[r][kk + 2*tq];
                bf[nt][1] = *(const unsigned*)&Bs[r][kk + 2*tq + 8];
            }
            #pragma unroll
            for (int mt = 0; mt < 4; ++mt)
                #pragma unroll
                for (int nt = 0; nt < 4; ++nt)
                    mma_16816(acc[mt][nt], af[mt], bf[nt]);
        }
        __syncthreads();
    }

    // Gate-interleaved epilogue: g_xg[row*G4 + j*4 + gate]
    #pragma unroll
    for (int mt = 0; mt < 4; ++mt) {
        #pragma unroll
        for (int nt = 0; nt < 4; ++nt) {
            int row = bm + wm + mt*16 + g;
            int col = bn + wn + nt*8 + 2*tq;
            int gate = col >> 11;
            int j    = col & 2047;
            float b0 = bi[col]   + bh[col];
            float b1 = bi[col+1] + bh[col+1];
            size_t i0  = (size_t)row*G4 + ((size_t)j << 2) + gate;
            size_t i08 = i0 + (size_t)8*G4;
            g_xg[i0]      = acc[mt][nt][0] + b0;
            g_xg[i0 + 4]  = acc[mt][nt][1] + b1;
            g_xg[i08]     = acc[mt][nt][2] + b0;
            g_xg[i08 + 4] = acc[mt][nt][3] + b1;
        }
    }
}

// ---------------- h0 conversion (both layers, once) ----------------
__global__ void init_h0(const float* __restrict__ h0) {
    int i = blockIdx.x*blockDim.x + threadIdx.x;
    if (i < 2*HD) g_h0h[i >> 11][i & 2047] = __float2half(h0[i]);
}

__device__ __forceinline__ float sigf(float x) { return 1.f / (1.f + __expf(-x)); }

// Fast, safe tanh: sign(x) * (1-e)/(1+e), e = exp(-2|x|) in (0,1]
__device__ __forceinline__ float tanhfast(float x) {
    float a = fabsf(x);
    float e = __expf(-2.f * a);
    float r = __fdividef(1.f - e, 1.f + e);
    return copysignf(r, x);
}

__device__ __forceinline__ float hsum4(const __half2 s[4]) {
    float2 f0 = __half22float2(s[0]);
    float2 f1 = __half22float2(s[1]);
    float2 f2 = __half22float2(s[2]);
    float2 f3 = __half22float2(s[3]);
    return ((f0.x + f0.y) + (f1.x + f1.y)) + ((f2.x + f2.y) + (f3.x + f3.y));
}

// HFMA2 dot against register-resident h (hreg[8] uint4), weights from SMEM.
#define COMPUTE_DOTS_REG(W0, W1, W2, W3)                                       \
    do {                                                                       \
        _Pragma("unroll")                                                      \
        for (int k = 0; k < 4; ++k) { s0[k] = z; s1[k] = z; s2[k] = z; s3[k] = z; } \
        _Pragma("unroll")                                                      \
        for (int it = 0; it < 8; ++it) {                                       \
            const int col = it*256 + lane*8;                                   \
            uint4 v0 = *(const uint4*)((W0) + col);                            \
            uint4 v1 = *(const uint4*)((W1) + col);                            \
            uint4 v2 = *(const uint4*)((W2) + col);                            \
            uint4 v3 = *(const uint4*)((W3) + col);                            \
            const __half2* hp = (const __half2*)&hreg[it];                     \
            const __half2* p0 = (const __half2*)&v0;                           \
            const __half2* p1 = (const __half2*)&v1;                           \
            const __half2* p2 = (const __half2*)&v2;                           \
            const __half2* p3 = (const __half2*)&v3;                           \
            _Pragma("unroll")                                                  \
            for (int k = 0; k < 4; ++k) {                                      \
                s0[k] = __hfma2(p0[k], hp[k], s0[k]);                          \
                s1[k] = __hfma2(p1[k], hp[k], s1[k]);                          \
                s2[k] = __hfma2(p2[k], hp[k], s2[k]);                          \
                s3[k] = __hfma2(p3[k], hp[k], s3[k]);                          \
            }                                                                  \
        }                                                                      \
    } while (0)

// ---------------- persistent weight-stationary LSTM recurrence ----------------
// 148 CTAs, 448 threads; CTA b owns nb = 14 (b<124) or 13 units, weights in SMEM.
// h loads use DEFAULT (L1-caching) loads: every h address is read exactly once
// per launch and only after the grid barrier ordered its writer's store to L2,
// so the first (only) access is a compulsory miss fetching fresh data; warps
// 1..13 of the SM then hit in L1 -> 14x less L2 traffic for the h broadcast.
// Barrier (R14-proven): tid0 fence -> red arrive -> volatile direct poll -> fence.
__global__ void __launch_bounds__(448, 1) lstm_recur(int layer, const float* __restrict__ c0all) {
    extern __shared__ __half ws[];          // up to 14 * 4 * HD halfs

    const int tid  = threadIdx.x;
    const int lane = tid & 31;
    const int wrp  = tid >> 5;
    const int b    = blockIdx.x;
    const int nb   = (b < 124) ? 14 : 13;
    const int start = b*13 + min(b, 124);
    const int j    = start + wrp;
    const bool valid = (wrp < nb);

    const __half* Whh  = g_whh + (size_t)layer*WSZ;
    __half*       Hout = layer ? g_h2 : g_h1;

    // Stage ALL nb units' weights into smem once per layer launch.
    {
        const int totq = nb << 10;          // nb*4*2048/8 uint4
        for (int idx = tid; idx < totq; idx += 448) {
            int u   = idx >> 10;
            int rem = idx & 1023;
            int g   = rem >> 8;
            int k   = (rem & 255) << 3;
            *(uint4*)(ws + ((size_t)(u*4 + g))*HD + k) =
                *(const uint4*)(Whh + (size_t)g*HD*HD + (size_t)(start + u)*HD + k);
        }
    }

    float c = valid ? c0all[layer*HD + j] : 0.f;

    __syncthreads();

    const __half2 z = __float2half2_rn(0.f);
    // Cumulative counter: layer 0 arrivals cover t=0..2046, layer 1 continues.
    const unsigned base = (unsigned)layer * (unsigned)(T_LEN - 1) * (unsigned)REC_CTAS;

    for (int t = 0; t < T_LEN; ++t) {
        // lane0 prefetch of input-gate vector (L1-cached; fresh address)
        float4 xv = make_float4(0.f, 0.f, 0.f, 0.f);
        if (valid && lane == 0)
            xv = ((const float4*)(g_xg + (size_t)t*G4))[j];

        // h_{t-1} -> registers: 8 MLP-overlapped 16B loads, L1-cached
        // (first warp misses to L2, subsequent warps hit L1)
        const uint4* hp4 = (const uint4*)((t == 0) ? g_h0h[layer] : (Hout + (size_t)(t-1)*HD));
        uint4 hreg[8];
        #pragma unroll
        for (int it = 0; it < 8; ++it)
            hreg[it] = hp4[it*32 + lane];

        __half2 s0[4], s1[4], s2[4], s3[4];
        if (valid) {
            const __half* w0 = ws + (size_t)(wrp*4)*HD;
            COMPUTE_DOTS_REG(w0, w0 + HD, w0 + 2*HD, w0 + 3*HD);
            float a0 = hsum4(s0), a1 = hsum4(s1), a2 = hsum4(s2), a3 = hsum4(s3);
            #pragma unroll
            for (int off = 16; off; off >>= 1) {
                a0 += __shfl_xor_sync(0xffffffffu, a0, off);
                a1 += __shfl_xor_sync(0xffffffffu, a1, off);
                a2 += __shfl_xor_sync(0xffffffffu, a2, off);
                a3 += __shfl_xor_sync(0xffffffffu, a3, off);
            }
            if (lane == 0) {
                float ig = sigf    (a0 + xv.x);
                float fg = sigf    (a1 + xv.y);
                float gg = tanhfast(a2 + xv.z);
                float og = sigf    (a3 + xv.w);
                c = fg * c + ig * gg;
                float h = og * tanhfast(c);
                Hout[(size_t)t * HD + j] = __float2half(h);
                if (t == T_LEN - 1) { g_hN[layer*HD + j] = h; g_cN[layer*HD + j] = c; }
                // no per-writer fence: tid0's release fence below covers the CTA
            }
        }

        if (t + 1 < T_LEN) {
            __syncthreads();                     // all warps' h stores issued
            if (tid == 0) {
                __threadfence();                 // release: CTA's stores visible before arrive
                red_add_u32(&g_cnt, 1u);         // arrive: fire-and-forget
                const unsigned target = base + (unsigned)REC_CTAS * (unsigned)(t + 1);
                volatile unsigned* vc = &g_cnt;  // STRONG direct poll (proven)
                while (*vc < target) {}
                __threadfence();                 // acquire before next step's reads
            }
            __syncthreads();
        }
    }
}

// ---------------- FC + log_softmax: one CTA per timestep ----------------
__global__ void __launch_bounds__(128) fc_logsoftmax(const float* __restrict__ fcb,
                                                     float* __restrict__ out) {
    const int t = blockIdx.x, v = threadIdx.x;
    __shared__ __align__(16) __half hsl[HD];
    __shared__ float lg[NV];
    __shared__ float red[NV];

    const uint4* src = (const uint4*)(g_h2 + (size_t)t * HD);
    ((uint4*)hsl)[v]       = src[v];
    ((uint4*)hsl)[v + 128] = src[v + 128];
    __syncthreads();

    float acc = fcb[v];
    const __half* wr = g_fcw + (size_t)v * HD;
    #pragma unroll 4
    for (int k = 0; k < HD; k += 8) {
        uint4 wv = *(const uint4*)(wr + k);
        uint4 hv = *(const uint4*)(hsl + k);
        float2 a, bb;
        a = __half22float2(*(const __half2*)&wv.x); bb = __half22float2(*(const __half2*)&hv.x); acc += a.x*bb.x + a.y*bb.y;
        a = __half22float2(*(const __half2*)&wv.y); bb = __half22float2(*(const __half2*)&hv.y); acc += a.x*bb.x + a.y*bb.y;
        a = __half22float2(*(const __half2*)&wv.z); bb = __half22float2(*(const __half2*)&hv.z); acc += a.x*bb.x + a.y*bb.y;
        a = __half22float2(*(const __half2*)&wv.w); bb = __half22float2(*(const __half2*)&hv.w); acc += a.x*bb.x + a.y*bb.y;
    }
    lg[v] = acc; red[v] = acc;
    __syncthreads();
    for (int s = 64; s > 0; s >>= 1) { if (v < s) red[v] = fmaxf(red[v], red[v + s]); __syncthreads(); }
    float mx = red[0];
    __syncthreads();
    red[v] = __expf(lg[v] - mx);
    __syncthreads();
    for (int s = 64; s > 0; s >>= 1) { if (v < s) red[v] += red[v + s]; __syncthreads(); }
    float lse = mx + logf(red[0]);
    out[(size_t)t * NV + v] = lg[v] - lse;
}

// ---------------- optional h_n / c_n tail ----------------
__global__ void write_states(float* __restrict__ out) {
    int i = blockIdx.x*blockDim.x + threadIdx.x;
    if (i < 2*HD) {
        out[(size_t)T_LEN*NV + i]        = g_hN[i];
        out[(size_t)T_LEN*NV + 2*HD + i] = g_cN[i];
    }
}

// ---------------- launcher ----------------
extern "C" void kernel_launch(void* const* d_in, const int* in_sizes, int n_in,
                              void* d_out, int out_size) {
    const float* x   = (const float*)d_in[0];
    const float* h0  = (const float*)d_in[1];
    const float* c0  = (const float*)d_in[2];
    const float* Wih = (const float*)d_in[3];
    const float* Whh = (const float*)d_in[4];
    const float* bih = (const float*)d_in[5];
    const float* bhh = (const float*)d_in[6];
    const float* fcw = (const float*)d_in[7];
    const float* fcb = (const float*)d_in[8];
    float* out = (float*)d_out;
    (void)in_sizes; (void)n_in;

    cudaFuncSetAttribute(lstm_recur, cudaFuncAttributeMaxDynamicSharedMemorySize, SMEM_REC);

    cvt_inputs<<<2048, 256>>>(x, Wih, Whh, fcw);
    init_h0<<<16, 256>>>(h0);

    dim3 ggrid(G4/128, T_LEN/128);
    for (int l = 0; l < 2; ++l) {
        gemm_ih<<<ggrid, 256>>>(l, bih, bhh);
        lstm_recur<<<REC_CTAS, 448, SMEM_REC>>>(l, c0);
    }

    fc_logsoftmax<<<T_LEN, 128>>>(fcb, out);

    if (out_size >= T_LEN*NV + 4*HD)
        write_states<<<(2*HD + 255)/256, 256>>>(out);
}